// round 7
// baseline (speedup 1.0000x reference)
#include <cuda_runtime.h>
#include <cuda_bf16.h>
#include <cstdint>

// Problem constants
#define N_ROWS 32768
#define DDIM   512
#define KCODES 4096

// Coarse tiling (bf16)
#define MTMAX 128              // max rows per CTA (some CTAs do 96)
#define NT 128                 // codes per chunk
#define BK 64                  // K bf16 per SMEM tile (128B rows)
#define NCHUNKS (KCODES / NT)          // 32
#define KT_PER_CHUNK (DDIM / BK)       // 8
#define TOTAL_TILES (NCHUNKS * KT_PER_CHUNK)  // 256
#define NSTG 3
#define STAGE_BYTES 32768      // A 16KB + B 16KB
#define SMEM_TOTAL (NSTG * STAGE_BYTES)

// Balanced grid: 296 CTAs (2/SM on 148 SMs). bid and bid+148 share an SM.
// bids 0..135:   128 rows  |  bids 148..283: 96 rows   (pair sum 224)
// bids 136..147:  96 rows  |  bids 284..295: 96 rows   (pair sum 192)
#define GRID_CTAS 296

// ---------------- scratch (A padded 32 rows: 96-row CTAs load full 128) -----
__device__ __nv_bfloat16 g_Ah[(size_t)(N_ROWS + 32) * DDIM];
__device__ __nv_bfloat16 g_Ch[(size_t)KCODES * DDIM];
__device__ float g_cnorm[KCODES];
__device__ int   g_cand[N_ROWS * 4];

// ---------------- PTX helpers ----------------
__device__ __forceinline__ uint32_t smem_to_u32(const void* p) {
    uint32_t a;
    asm("{ .reg .u64 t; cvta.to.shared.u64 t, %1; cvt.u32.u64 %0, t; }" : "=r"(a) : "l"(p));
    return a;
}
__device__ __forceinline__ void cp_async16(uint32_t dst, const void* src) {
    asm volatile("cp.async.cg.shared.global [%0], [%1], 16;" :: "r"(dst), "l"(src) : "memory");
}
#define CP_COMMIT() asm volatile("cp.async.commit_group;" ::: "memory")
#define CP_WAIT(n)  asm volatile("cp.async.wait_group %0;" :: "n"(n) : "memory")

__device__ __forceinline__ void ldsm_x4(uint32_t& r0, uint32_t& r1, uint32_t& r2,
                                        uint32_t& r3, uint32_t addr) {
    asm volatile("ldmatrix.sync.aligned.m8n8.x4.shared.b16 {%0,%1,%2,%3}, [%4];"
                 : "=r"(r0), "=r"(r1), "=r"(r2), "=r"(r3) : "r"(addr));
}
__device__ __forceinline__ void mma16816(float* d, const uint32_t* a,
                                         uint32_t b0, uint32_t b1) {
    asm volatile(
        "mma.sync.aligned.m16n8k16.row.col.f32.bf16.bf16.f32 "
        "{%0,%1,%2,%3}, {%4,%5,%6,%7}, {%8,%9}, {%0,%1,%2,%3};"
        : "+f"(d[0]), "+f"(d[1]), "+f"(d[2]), "+f"(d[3])
        : "r"(a[0]), "r"(a[1]), "r"(a[2]), "r"(a[3]), "r"(b0), "r"(b1));
}
__device__ __forceinline__ uint32_t sw_off(int row, int chunk) {
    return (uint32_t)(row * 128 + ((chunk ^ (row & 7)) << 4));
}

// ---------------------------------------------------------------------------
// Precompute: inputs fp32 -> bf16
// ---------------------------------------------------------------------------
__global__ void split_inputs_kernel(const float* __restrict__ src) {
    int n4 = N_ROWS * DDIM / 4;
    for (int i = blockIdx.x * blockDim.x + threadIdx.x; i < n4; i += gridDim.x * blockDim.x) {
        float4 v = reinterpret_cast<const float4*>(src)[i];
        __nv_bfloat16 h[4] = {__float2bfloat16_rn(v.x), __float2bfloat16_rn(v.y),
                              __float2bfloat16_rn(v.z), __float2bfloat16_rn(v.w)};
        reinterpret_cast<uint2*>(g_Ah)[i] = *reinterpret_cast<uint2*>(h);
    }
}
// Codebook -> bf16 AND ||c||^2, one pass. 128 thr per row.
__global__ void quant_codebook_kernel(const float* __restrict__ cb) {
    int k = blockIdx.x;
    float4 v = reinterpret_cast<const float4*>(cb + (size_t)k * DDIM)[threadIdx.x];
    __nv_bfloat16 h[4] = {__float2bfloat16_rn(v.x), __float2bfloat16_rn(v.y),
                          __float2bfloat16_rn(v.z), __float2bfloat16_rn(v.w)};
    reinterpret_cast<uint2*>(g_Ch)[k * (DDIM / 4) + threadIdx.x] =
        *reinterpret_cast<uint2*>(h);
    float s = v.x * v.x + v.y * v.y + v.z * v.z + v.w * v.w;
#pragma unroll
    for (int o = 16; o > 0; o >>= 1) s += __shfl_xor_sync(0xffffffffu, s, o);
    __shared__ float ws[4];
    if ((threadIdx.x & 31) == 0) ws[threadIdx.x >> 5] = s;
    __syncthreads();
    if (threadIdx.x == 0) g_cnorm[k] = ws[0] + ws[1] + ws[2] + ws[3];
}

// ---------------------------------------------------------------------------
// Coarse pass: bf16 GEMM + per-thread top-2 per row-slot.
// 296 CTAs x 256 threads, 2 CTAs/SM. 8 warps (4m x 2n), warp tile 32x64.
// ---------------------------------------------------------------------------
__device__ __forceinline__ void issue_stage(uint32_t aBase, uint32_t bBase,
                                            int r0, int c0, int ks, int tid) {
#pragma unroll
    for (int i = 0; i < 4; ++i) {
        int idx = tid + i * 256;        // 0..1023
        int row = idx >> 3, ch = idx & 7;
        cp_async16(aBase + sw_off(row, ch),
                   g_Ah + (size_t)(r0 + row) * DDIM + ks + ch * 8);
    }
#pragma unroll
    for (int i = 0; i < 4; ++i) {
        int idx = tid + i * 256;
        int row = idx >> 3, ch = idx & 7;
        cp_async16(bBase + sw_off(row, ch),
                   g_Ch + (size_t)(c0 + row) * DDIM + ks + ch * 8);
    }
    CP_COMMIT();
}

__global__ void __launch_bounds__(256, 2)
vq_coarse_kernel() {
    extern __shared__ char smem[];
    const uint32_t sb = smem_to_u32(smem);
    const int tid  = threadIdx.x;
    const int lane = tid & 31;
    const int warp = tid >> 5;
    const int wm = warp >> 1;          // 0..3 (32 rows each)
    const int wn = warp & 1;           // 0..1 (64 codes each)

    // Balanced (r0, mt) mapping
    const int bid = blockIdx.x;
    int r0, mt;
    if (bid < 136)      { r0 = bid * 128;                 mt = 128; }
    else if (bid < 148) { r0 = 17408 + (bid - 136) * 96;  mt = 96;  }
    else if (bid < 284) { r0 = 18560 + (bid - 148) * 96;  mt = 96;  }
    else                { r0 = 31616 + (bid - 284) * 96;  mt = 96;  }
    const bool active = (wm * 32) < mt;

    const int sub  = lane >> 3;
    const int lrow = (sub & 1) * 8 + (lane & 7);
    const int lchk = sub >> 1;

    float acc[2][8][4];
#pragma unroll
    for (int mi = 0; mi < 2; ++mi)
#pragma unroll
        for (int n8 = 0; n8 < 8; ++n8)
#pragma unroll
            for (int e = 0; e < 4; ++e) acc[mi][n8][e] = 0.f;

    // per row-slot top-2 (4 slots: mi*2 + rowhalf)
    float v0[4], v1[4];
    int   i0[4], i1[4];
#pragma unroll
    for (int s = 0; s < 4; ++s) { v0[s] = v1[s] = 3.0e38f; i0[s] = i1[s] = 0x7fffffff; }

    issue_stage(sb, sb + 16384, r0, 0, 0, tid);
    issue_stage(sb + STAGE_BYTES, sb + STAGE_BYTES + 16384, r0, 0, BK, tid);

#pragma unroll 1
    for (int t = 0; t < TOTAL_TILES; ++t) {
        const int chunk = t >> 3;
        const int kt = t & 7;

        if (t == TOTAL_TILES - 1) { CP_WAIT(0); } else { CP_WAIT(1); }
        __syncthreads();

        if (t + 2 < TOTAL_TILES) {
            const int t2 = t + 2;
            const int s2 = t2 % NSTG;
            issue_stage(sb + s2 * STAGE_BYTES, sb + s2 * STAGE_BYTES + 16384,
                        r0, (t2 >> 3) * NT, (t2 & 7) * BK, tid);
        }

        if (active) {
            const uint32_t aBase = sb + (t % NSTG) * STAGE_BYTES;
            const uint32_t bBase = aBase + 16384;
#pragma unroll
            for (int kk = 0; kk < 4; ++kk) {
                uint32_t a[2][4];
#pragma unroll
                for (int mi = 0; mi < 2; ++mi)
                    ldsm_x4(a[mi][0], a[mi][1], a[mi][2], a[mi][3],
                            aBase + sw_off(wm * 32 + mi * 16 + lrow, kk * 2 + lchk));
                uint32_t bfr[4][4];
#pragma unroll
                for (int ni = 0; ni < 4; ++ni)
                    ldsm_x4(bfr[ni][0], bfr[ni][1], bfr[ni][2], bfr[ni][3],
                            bBase + sw_off(wn * 64 + ni * 16 + lrow, kk * 2 + lchk));
#pragma unroll
                for (int mi = 0; mi < 2; ++mi)
#pragma unroll
                    for (int n8 = 0; n8 < 8; ++n8)
                        mma16816(acc[mi][n8], a[mi],
                                 bfr[n8 >> 1][n8 & 1], bfr[n8 >> 1][(n8 & 1) + 2]);
            }

            if (kt == KT_PER_CHUNK - 1) {
                const int c0 = chunk * NT;
#pragma unroll
                for (int n8 = 0; n8 < 8; ++n8) {
                    const int col = c0 + wn * 64 + n8 * 8 + 2 * (lane & 3);
                    const float cn0 = __ldg(&g_cnorm[col]);
                    const float cn1 = __ldg(&g_cnorm[col + 1]);
#pragma unroll
                    for (int mi = 0; mi < 2; ++mi) {
#pragma unroll
                        for (int e = 0; e < 4; ++e) {
                            const int slot = mi * 2 + (e >> 1);
                            const float cn = (e & 1) ? cn1 : cn0;
                            const int   cx = col + (e & 1);
                            float d = fmaf(-2.f, acc[mi][n8][e], cn);
                            if (d < v1[slot]) {
                                if (d < v0[slot]) {
                                    v1[slot] = v0[slot]; i1[slot] = i0[slot];
                                    v0[slot] = d;        i0[slot] = cx;
                                } else { v1[slot] = d; i1[slot] = cx; }
                            }
                            acc[mi][n8][e] = 0.f;
                        }
                    }
                }
            }
        }
    }

    // Merge 8 threads x 2 entries per row -> global top-4 per row
    __syncthreads();
    float* mv = reinterpret_cast<float*>(smem);            // [128][16]
    int*   md = reinterpret_cast<int*>(smem + 8192);       // [128][16]
    if (active) {
#pragma unroll
        for (int slot = 0; slot < 4; ++slot) {
            const int mi = slot >> 1, rh = slot & 1;
            const int row = wm * 32 + mi * 16 + rh * 8 + (lane >> 2);
            const int col = wn * 8 + (lane & 3) * 2;
            mv[row * 16 + col]     = v0[slot];
            md[row * 16 + col]     = i0[slot];
            mv[row * 16 + col + 1] = v1[slot];
            md[row * 16 + col + 1] = i1[slot];
        }
    }
    __syncthreads();
    if (tid < mt) {
        float tv[4] = {3.0e38f, 3.0e38f, 3.0e38f, 3.0e38f};
        int   ti[4] = {0x7fffffff, 0x7fffffff, 0x7fffffff, 0x7fffffff};
#pragma unroll 4
        for (int e = 0; e < 16; ++e) {
            float v = mv[tid * 16 + e];
            int   d = md[tid * 16 + e];
            if (v < tv[3] || (v == tv[3] && d < ti[3])) {
                tv[3] = v; ti[3] = d;
#pragma unroll
                for (int j = 3; j >= 1; --j) {
                    if (tv[j] < tv[j-1] || (tv[j] == tv[j-1] && ti[j] < ti[j-1])) {
                        float fv = tv[j]; tv[j] = tv[j-1]; tv[j-1] = fv;
                        int   fi = ti[j]; ti[j] = ti[j-1]; ti[j-1] = fi;
                    }
                }
            }
        }
#pragma unroll
        for (int j = 0; j < 4; ++j) g_cand[(r0 + tid) * 4 + j] = ti[j];
    }
}

// ---------------------------------------------------------------------------
// Exact refine + gather. One warp per row; 4 candidates, fp32 dots.
// ---------------------------------------------------------------------------
__global__ void __launch_bounds__(256)
refine_kernel(const float* __restrict__ cb, const float* __restrict__ x,
              float* __restrict__ out) {
    const int n = blockIdx.x * 8 + (threadIdx.x >> 5);
    const int lane = threadIdx.x & 31;

    float xr[16];
#pragma unroll
    for (int j = 0; j < 16; ++j) xr[j] = x[(size_t)n * DDIM + j * 32 + lane];

    float bv = 3.0e38f;
    int   bi = 0x7fffffff;
#pragma unroll
    for (int c = 0; c < 4; ++c) {
        const int k = g_cand[n * 4 + c];
        const float* crow = cb + (size_t)k * DDIM;
        float s = 0.f;
#pragma unroll
        for (int j = 0; j < 16; ++j) s = fmaf(xr[j], __ldg(crow + j * 32 + lane), s);
#pragma unroll
        for (int o = 16; o > 0; o >>= 1) s += __shfl_xor_sync(0xffffffffu, s, o);
        float d2 = fmaf(-2.f, s, __ldg(&g_cnorm[k]));
        if (d2 < bv || (d2 == bv && k < bi)) { bv = d2; bi = k; }
    }

    const float* q = cb + (size_t)bi * DDIM;
#pragma unroll
    for (int j = 0; j < 16; ++j) {
        float qv = __ldg(q + j * 32 + lane);
        float xv = xr[j];
        out[(size_t)n * DDIM + j * 32 + lane] = (qv - xv) + xv;
    }
}

// ---------------------------------------------------------------------------
extern "C" void kernel_launch(void* const* d_in, const int* in_sizes, int n_in,
                              void* d_out, int out_size) {
    const float* inputs   = (const float*)d_in[0];
    const float* codebook = (const float*)d_in[1];
    float* out = (float*)d_out;

    cudaFuncSetAttribute(vq_coarse_kernel, cudaFuncAttributeMaxDynamicSharedMemorySize,
                         SMEM_TOTAL);

    split_inputs_kernel<<<4096, 256>>>(inputs);
    quant_codebook_kernel<<<KCODES, 128>>>(codebook);
    vq_coarse_kernel<<<GRID_CTAS, 256, SMEM_TOTAL>>>();
    refine_kernel<<<N_ROWS / 8, 256>>>(codebook, inputs, out);
}